// round 10
// baseline (speedup 1.0000x reference)
#include <cuda_runtime.h>
#include <cuda_bf16.h>
#include <cstdint>
#include <cstddef>

// ============================================================================
// RNN_4715874091371 — GB300 sm_103a (compute_103 PTX)
//   Z = X @ W_ih^T + (b_ih+b_hh)   bf16 m16n8k16 GEMM, ldmatrix fragments
//   h_t = tanh(Z_t + h_{t-1} @ W_hh^T)  persistent bf16 kernel, 256 CTAs,
//       CTA tile 64x64, 2 CTAs/SM, A+B streamed, per-m-group barriers
//   p = sigmoid(h @ W_out^T + b_out);  loss = BCE(p, y >= 1e-5)
// ============================================================================

static constexpr int TT = 64;
static constexpr int BB = 1024;
static constexpr int HH = 1024;

// ---------------- device scratch (allocation-free rule) --------------------
__device__ __nv_bfloat16 g_Xbf[(size_t)BB * TT * HH];    // av in bf16 (128MB)
__device__ __nv_bfloat16 g_Wihbf[(size_t)HH * HH];       // W_ih bf16
__device__ __nv_bfloat16 g_Whhbf[(size_t)HH * HH];       // W_hh bf16
__device__ float g_Z[(size_t)TT * BB * HH];               // [t][b][h] fp32
__device__ __nv_bfloat16 g_hbf[2][(size_t)BB * HH];       // ping-pong hidden
__device__ float g_p[BB];
__device__ unsigned g_bars[16];                            // per-m-group

#define DEVI __device__ __forceinline__

DEVI uint32_t smem_u32(const void* p) {
    uint32_t a;
    asm("{ .reg .u64 t; cvta.to.shared.u64 t, %1; cvt.u32.u64 %0, t; }"
        : "=r"(a) : "l"(p));
    return a;
}

#define CPA16(dst_b, src) \
    asm volatile("cp.async.cg.shared.global [%0], [%1], 16;" :: "r"(dst_b), "l"(src))
#define CPC()    asm volatile("cp.async.commit_group;" ::: "memory")
#define CPW2()   asm volatile("cp.async.wait_group 2;" ::: "memory")

// bf16 m16n8k16: D += A*B
#define MMA_BF16(d, a, b)                                                       \
    asm("mma.sync.aligned.m16n8k16.row.col.f32.bf16.bf16.f32 "                  \
        "{%0,%1,%2,%3}, {%4,%5,%6,%7}, {%8,%9}, {%0,%1,%2,%3};"                 \
        : "+f"((d)[0]), "+f"((d)[1]), "+f"((d)[2]), "+f"((d)[3])                \
        : "r"((a)[0]), "r"((a)[1]), "r"((a)[2]), "r"((a)[3]),                   \
          "r"((b)[0]), "r"((b)[1]))

// ldmatrix x4: d[0..3] <- four 8x8 b16 matrices
#define LDSM4(d, addr)                                                          \
    asm volatile("ldmatrix.sync.aligned.m8n8.x4.shared.b16 {%0,%1,%2,%3}, [%4];"\
        : "=r"((d)[0]), "=r"((d)[1]), "=r"((d)[2]), "=r"((d)[3]) : "r"(addr))

// ============================================================================
// Big GEMM (bf16): Z = Xbf @ Wihbf^T + (b_ih+b_hh). Tile 128x128, K-chunk 64
// halves (32 words/row, pad 36), 16 chunks, 3 stages, 2 CTAs/SM, ldmatrix.
// ============================================================================
__global__ __launch_bounds__(256, 2)
void gemm_big(const float* __restrict__ bih, const float* __restrict__ bhh)
{
    constexpr int SASZ = 128 * 36, SBSZ = 128 * 36, STG = SASZ + SBSZ; // words
    extern __shared__ __align__(16) uint32_t sm[];
    const uint32_t smb = smem_u32(sm);

    const int tid  = threadIdx.x;
    const int lane = tid & 31;
    const int wid  = tid >> 5;
    const int wm   = wid >> 2;             // 2 x 4 warp grid; warp tile 64x32
    const int wn   = wid & 3;
    const int n0   = blockIdx.x * 128;
    const int m0   = blockIdx.y * 128;

    const int lrA = lane & 15;
    const int whA = (lane >> 4) * 4;
    const int lrB = (lane & 7) | ((lane >> 4) << 3);
    const int wB  = ((lane >> 3) & 1) * 4;

    auto load_stage = [&](int c, int s) {
        const int kf = c * 64;                               // in halves
        const uint32_t ab = smb + (uint32_t)(s * STG) * 4;
        const uint32_t bb = ab + (uint32_t)SASZ * 4;
        #pragma unroll
        for (int i = 0; i < 4; ++i) {                        // A: 128 x 128B
            int e = tid + i * 256, r = e >> 3, j = e & 7;
            CPA16(ab + (uint32_t)(r * 36 + j * 4) * 4,
                  g_Xbf + (size_t)(m0 + r) * HH + kf + j * 8);
        }
        #pragma unroll
        for (int i = 0; i < 4; ++i) {                        // B: 128 x 128B
            int e = tid + i * 256, r = e >> 3, j = e & 7;
            CPA16(bb + (uint32_t)(r * 36 + j * 4) * 4,
                  g_Wihbf + (size_t)(n0 + r) * HH + kf + j * 8);
        }
    };

    #pragma unroll
    for (int c = 0; c < 3; ++c) { load_stage(c, c); CPC(); }

    float acc[4][4][4];
    #pragma unroll
    for (int mi = 0; mi < 4; ++mi)
        #pragma unroll
        for (int nf = 0; nf < 4; ++nf)
            #pragma unroll
            for (int j = 0; j < 4; ++j) acc[mi][nf][j] = 0.f;

    for (int c = 0; c < 16; ++c) {
        CPW2();
        __syncthreads();
        const uint32_t sA = smb + (uint32_t)((c % 3) * STG) * 4;
        const uint32_t sB = sA + (uint32_t)SASZ * 4;
        #pragma unroll
        for (int ks = 0; ks < 4; ++ks) {                     // k16 per MMA
            uint32_t a[4][4];
            #pragma unroll
            for (int mi = 0; mi < 4; ++mi)
                LDSM4(a[mi], sA + (uint32_t)((wm * 64 + mi * 16 + lrA) * 36
                                             + ks * 8 + whA) * 4);
            uint32_t b[4][2];
            #pragma unroll
            for (int nfp = 0; nfp < 2; ++nfp)
                LDSM4((&b[2 * nfp][0]),
                      sB + (uint32_t)((wn * 32 + nfp * 16 + lrB) * 36
                                      + ks * 8 + wB) * 4);
            #pragma unroll
            for (int mi = 0; mi < 4; ++mi)
                #pragma unroll
                for (int nf = 0; nf < 4; ++nf)
                    MMA_BF16(acc[mi][nf], a[mi], b[nf]);
        }
        __syncthreads();
        if (c + 3 < 16) load_stage(c + 3, c % 3);
        CPC();
    }

    // epilogue: + biases, scatter to g_Z[t][b][n]  (m = b*64 + t)
    const int arow = lane >> 2, q = lane & 3;
    #pragma unroll
    for (int mi = 0; mi < 4; ++mi) {
        const int r0 = m0 + wm * 64 + mi * 16 + arow;
        #pragma unroll
        for (int nf = 0; nf < 4; ++nf) {
            const int cg = n0 + wn * 32 + nf * 8 + q * 2;
            const float bsum0 = bih[cg] + bhh[cg];
            const float bsum1 = bih[cg + 1] + bhh[cg + 1];
            #pragma unroll
            for (int half = 0; half < 2; ++half) {
                const int r = r0 + half * 8;
                float2 o;
                o.x = acc[mi][nf][half * 2 + 0] + bsum0;
                o.y = acc[mi][nf][half * 2 + 1] + bsum1;
                const int b = r >> 6, t = r & 63;
                *(float2*)(g_Z + ((size_t)t * BB + b) * HH + cg) = o;
            }
        }
    }
}

// ============================================================================
// Persistent steps (bf16): 256 CTAs (16 m-groups x 16 n-tiles), CTA tile
// 64x64, 2 CTAs/SM, warp grid 2x4 (warp tile 32x16). A (=h) and B (=W_hh)
// streamed from L2, K-chunk 64 halves, 4 stages, single sync/chunk,
// ldmatrix fragments, per-m-group barriers (16 CTAs each).
// ============================================================================
__global__ __launch_bounds__(256, 2)
void steps_k()
{
    constexpr int ASZ = 64 * 36;                   // words per A stage
    constexpr int STG = 2 * ASZ;                   // A+B per stage
    extern __shared__ __align__(16) uint32_t sm[];
    const uint32_t smb = smem_u32(sm);

    const int tid  = threadIdx.x;
    const int lane = tid & 31;
    const int wid  = tid >> 5;
    const int wm   = wid >> 2;             // 2 x 4 warp grid; warp tile 32x16
    const int wn   = wid & 3;
    const int mg   = blockIdx.x >> 4;      // m-group 0..15
    const int m0   = mg * 64;
    const int n0   = (blockIdx.x & 15) * 64;

    // ---- t = 0: h0 = tanh(Z_0) on this CTA's tile (64 x 64) ----
    for (int e = tid; e < 64 * 64; e += 256) {
        int r = e >> 6, c = e & 63;
        size_t idx = (size_t)(m0 + r) * HH + n0 + c;
        g_hbf[0][idx] = __float2bfloat16_rn(tanhf(g_Z[idx]));
    }
    __syncthreads();
    if (tid == 0) { __threadfence(); atomicAdd(&g_bars[mg], 1); }

    const int arow = lane >> 2, q = lane & 3;
    const int lrA = lane & 15;
    const int whA = (lane >> 4) * 4;
    const int lrB = (lane & 7) | ((lane >> 4) << 3);
    const int wB  = ((lane >> 3) & 1) * 4;

    for (int t = 1; t < TT; ++t) {
        const __nv_bfloat16* __restrict__ Asrc = g_hbf[(t - 1) & 1];
        __nv_bfloat16*       __restrict__ out  = g_hbf[t & 1];
        const float*         __restrict__ Zt   = g_Z + (size_t)t * BB * HH;

        // Z prefetch (independent of h): hide behind barrier wait
        float2 zf[2][2][2];
        #pragma unroll
        for (int mi = 0; mi < 2; ++mi)
            #pragma unroll
            for (int nf = 0; nf < 2; ++nf) {
                const int cg = n0 + wn * 16 + nf * 8 + q * 2;
                #pragma unroll
                for (int half = 0; half < 2; ++half) {
                    const int r = m0 + wm * 32 + mi * 16 + arow + half * 8;
                    zf[mi][nf][half] = *(const float2*)(Zt + (size_t)r * HH + cg);
                }
            }

        // per-m-group barrier: 16 CTAs of this group wrote h_{t-1}
        if (tid == 0) {
            const unsigned tgt = 16u * (unsigned)t;
            while (*(volatile unsigned*)&g_bars[mg] < tgt) __nanosleep(32);
            __threadfence();
        }
        __syncthreads();

        // stage loader: chunk c (64 halves) -> slot s  (A rows=h, B rows=Whh)
        auto load_stage = [&](int c, int s) {
            const int kf = c * 64;
            const uint32_t ab = smb + (uint32_t)(s * STG) * 4;
            const uint32_t bb = ab + (uint32_t)ASZ * 4;
            #pragma unroll
            for (int i = 0; i < 2; ++i) {                    // A: 64 x 128B
                int e = tid + i * 256, r = e >> 3, j = e & 7;
                CPA16(ab + (uint32_t)(r * 36 + j * 4) * 4,
                      Asrc + (size_t)(m0 + r) * HH + kf + j * 8);
            }
            #pragma unroll
            for (int i = 0; i < 2; ++i) {                    // B: 64 x 128B
                int e = tid + i * 256, r = e >> 3, j = e & 7;
                CPA16(bb + (uint32_t)(r * 36 + j * 4) * 4,
                      g_Whhbf + (size_t)(n0 + r) * HH + kf + j * 8);
            }
        };

        #pragma unroll
        for (int c = 0; c < 3; ++c) { load_stage(c, c); CPC(); }

        float acc[2][2][4];
        #pragma unroll
        for (int mi = 0; mi < 2; ++mi)
            #pragma unroll
            for (int nf = 0; nf < 2; ++nf)
                #pragma unroll
                for (int j = 0; j < 4; ++j) acc[mi][nf][j] = 0.f;

        for (int c = 0; c < 16; ++c) {
            CPW2();                       // chunk c landed
            __syncthreads();              // all warps done with slot (c-1)&3
            if (c + 3 < 16) load_stage(c + 3, (c + 3) & 3);
            CPC();
            const uint32_t sA = smb + (uint32_t)((c & 3) * STG) * 4;
            const uint32_t sB = sA + (uint32_t)ASZ * 4;
            #pragma unroll
            for (int ks = 0; ks < 4; ++ks) {                 // k16 per MMA
                uint32_t a[2][4];
                #pragma unroll
                for (int mi = 0; mi < 2; ++mi)
                    LDSM4(a[mi], sA + (uint32_t)((wm * 32 + mi * 16 + lrA) * 36
                                                 + ks * 8 + whA) * 4);
                uint32_t b[2][2];
                LDSM4((&b[0][0]),
                      sB + (uint32_t)((wn * 16 + lrB) * 36 + ks * 8 + wB) * 4);
                #pragma unroll
                for (int mi = 0; mi < 2; ++mi)
                    #pragma unroll
                    for (int nf = 0; nf < 2; ++nf)
                        MMA_BF16(acc[mi][nf], a[mi], b[nf]);
            }
        }

        // epilogue: tanh(acc + Z_t) -> bf16 h[t&1]
        #pragma unroll
        for (int mi = 0; mi < 2; ++mi)
            #pragma unroll
            for (int nf = 0; nf < 2; ++nf) {
                const int cg = n0 + wn * 16 + nf * 8 + q * 2;
                #pragma unroll
                for (int half = 0; half < 2; ++half) {
                    const int r = m0 + wm * 32 + mi * 16 + arow + half * 8;
                    float ox = tanhf(acc[mi][nf][half * 2 + 0] + zf[mi][nf][half].x);
                    float oy = tanhf(acc[mi][nf][half * 2 + 1] + zf[mi][nf][half].y);
                    __nv_bfloat162 o2 = __floats2bfloat162_rn(ox, oy);
                    *(__nv_bfloat162*)(out + (size_t)r * HH + cg) = o2;
                }
            }
        __syncthreads();
        if (tid == 0) { __threadfence(); atomicAdd(&g_bars[mg], 1); }
    }
}

// ----------------------------- small kernels --------------------------------
__global__ void conv_av_k(const float4* __restrict__ av, int n8) {
    int i = blockIdx.x * blockDim.x + threadIdx.x;       // 8 floats per thread
    if (i < n8) {
        float4 a = av[2 * i], b = av[2 * i + 1];
        __nv_bfloat162 p0 = __floats2bfloat162_rn(a.x, a.y);
        __nv_bfloat162 p1 = __floats2bfloat162_rn(a.z, a.w);
        __nv_bfloat162 p2 = __floats2bfloat162_rn(b.x, b.y);
        __nv_bfloat162 p3 = __floats2bfloat162_rn(b.z, b.w);
        uint4 o = make_uint4(*(uint32_t*)&p0, *(uint32_t*)&p1,
                             *(uint32_t*)&p2, *(uint32_t*)&p3);
        ((uint4*)g_Xbf)[i] = o;
    }
}

__global__ void conv_W_k(const float4* __restrict__ wih,
                         const float4* __restrict__ whh, int n4) {
    int i = blockIdx.x * blockDim.x + threadIdx.x;
    if (i < 16) g_bars[i] = 0;                            // reset barriers
    if (i < n4) {
        float4 a = wih[i];
        __nv_bfloat162 p0 = __floats2bfloat162_rn(a.x, a.y);
        __nv_bfloat162 p1 = __floats2bfloat162_rn(a.z, a.w);
        ((uint2*)g_Wihbf)[i] = make_uint2(*(uint32_t*)&p0, *(uint32_t*)&p1);
        float4 b = whh[i];
        __nv_bfloat162 q0 = __floats2bfloat162_rn(b.x, b.y);
        __nv_bfloat162 q1 = __floats2bfloat162_rn(b.z, b.w);
        ((uint2*)g_Whhbf)[i] = make_uint2(*(uint32_t*)&q0, *(uint32_t*)&q1);
    }
}

__global__ void head_k(const float* __restrict__ Wout,
                       const float* __restrict__ bout) {
    int wid = threadIdx.x >> 5, lane = threadIdx.x & 31;
    int row = blockIdx.x * 8 + wid;
    const __nv_bfloat162* hr =
        (const __nv_bfloat162*)(g_hbf[1] + (size_t)row * HH);
    const float2* wr = (const float2*)Wout;
    float s = 0.f;
    for (int i = lane; i < HH / 2; i += 32) {
        float2 hv = __bfloat1622float2(hr[i]);
        float2 wv = wr[i];
        s += hv.x * wv.x + hv.y * wv.y;
    }
    #pragma unroll
    for (int o = 16; o; o >>= 1) s += __shfl_xor_sync(0xFFFFFFFFu, s, o);
    if (lane == 0) g_p[row] = 1.f / (1.f + expf(-(s + bout[0])));
}

__global__ void loss_k(const float* __restrict__ y, float* __restrict__ out,
                       int out_size) {
    __shared__ float red[32];
    int tid = threadIdx.x;                                // 1024 threads
    float pv = g_p[tid];
    float yb = (y[tid] >= 1e-5f) ? 1.f : 0.f;
    float term = yb * fmaxf(logf(pv), -100.f)
               + (1.f - yb) * fmaxf(log1pf(-pv), -100.f);
    #pragma unroll
    for (int o = 16; o; o >>= 1) term += __shfl_xor_sync(0xFFFFFFFFu, term, o);
    if ((tid & 31) == 0) red[tid >> 5] = term;
    __syncthreads();
    if (tid < 32) {
        float v = red[tid];
        #pragma unroll
        for (int o = 16; o; o >>= 1) v += __shfl_xor_sync(0xFFFFFFFFu, v, o);
        if (tid == 0 && out_size != BB) out[0] = -v / (float)BB;
    }
    if (out_size >= 1 + BB)      out[1 + tid] = pv;
    else if (out_size == BB)     out[tid] = pv;
    for (int i = 1 + BB + tid; i < out_size; i += BB) out[i] = 0.f;
}

// ------------------------------- launcher -----------------------------------
extern "C" void kernel_launch(void* const* d_in, const int* in_sizes, int n_in,
                              void* d_out, int out_size) {
    const float* av   = (const float*)d_in[3];
    const float* y    = (const float*)d_in[4];
    const float* Wih  = (const float*)d_in[5];
    const float* bih  = (const float*)d_in[6];
    const float* Whh  = (const float*)d_in[7];
    const float* bhh  = (const float*)d_in[8];
    const float* Wout = (const float*)d_in[9];
    const float* bout = (const float*)d_in[10];
    (void)in_sizes; (void)n_in;

    constexpr int SMEM_BIG  = 3 * (128 * 36 + 128 * 36) * 4;     // 110592 B
    constexpr int SMEM_STEP = 4 * (64 * 36 + 64 * 36) * 4;       //  73728 B
    cudaFuncSetAttribute(gemm_big,
                         cudaFuncAttributeMaxDynamicSharedMemorySize, SMEM_BIG);
    cudaFuncSetAttribute(steps_k,
                         cudaFuncAttributeMaxDynamicSharedMemorySize, SMEM_STEP);

    // 1) conversions (av, W_ih, W_hh -> bf16) + barrier reset
    conv_av_k<<<(BB * TT * HH / 8 + 255) / 256, 256>>>((const float4*)av,
                                                       BB * TT * HH / 8);
    conv_W_k<<<(HH * HH / 4 + 255) / 256, 256>>>(
        (const float4*)Wih, (const float4*)Whh, HH * HH / 4);

    // 2) Z = X @ W_ih^T + b_ih + b_hh   (bf16 tensor cores)
    gemm_big<<<dim3(8, 512), 256, SMEM_BIG>>>(bih, bhh);

    // 3) persistent recurrence (bf16), 2 CTAs/SM, per-group barriers
    steps_k<<<256, 256, SMEM_STEP>>>();

    // 4) head + loss (final h in g_hbf[1])
    head_k<<<128, 256>>>(Wout, bout);
    loss_k<<<1, BB>>>(y, (float*)d_out, out_size);
}